// round 2
// baseline (speedup 1.0000x reference)
#include <cuda_runtime.h>
#include <cstdint>

#define NTT 144
#define NTERMS 20                 // series coefficients d0..d19 (tail < 3e-6 abs)
#define ROWS_PER_BLK 8
#define THREADS_PER_ROW 36        // 36 * 4 elems = 144
#define BLK (ROWS_PER_BLK * THREADS_PER_ROW)  // 288
#define RC_STRIDE 28              // 4 scalars + 20 coeffs, padded (28 mod 32 != 0)

#define F_TAU 1.8f
#define F_INV_T1B (1.0f/1.65f)
#define F_LOG2E 1.4426950408889634f
#define F_DEG2RAD 0.017453292519943295f

__device__ __forceinline__ unsigned long long pack2(float lo, float hi) {
    unsigned long long r;
    asm("mov.b64 %0, {%1, %2};" : "=l"(r) : "f"(lo), "f"(hi));
    return r;
}
__device__ __forceinline__ void unpack2(unsigned long long v, float& lo, float& hi) {
    asm("mov.b64 {%0, %1}, %2;" : "=f"(lo), "=f"(hi) : "l"(v));
}
__device__ __forceinline__ unsigned long long ffma2(unsigned long long a,
                                                    unsigned long long b,
                                                    unsigned long long c) {
    unsigned long long d;
    asm("fma.rn.f32x2 %0, %1, %2, %3;" : "=l"(d) : "l"(a), "l"(b), "l"(c));
    return d;
}
__device__ __forceinline__ float fast_lg2(float x) {
    float r;
    asm("lg2.approx.f32 %0, %1;" : "=f"(r) : "f"(x));
    return r;
}
__device__ __forceinline__ float fast_ex2(float x) {
    float r;
    asm("ex2.approx.f32 %0, %1;" : "=f"(r) : "f"(x));
    return r;
}

__global__ __launch_bounds__(BLK)
void dynangio_kernel(const float4* __restrict__ x,
                     const float*  __restrict__ t,
                     const float*  __restrict__ alpha,
                     const float*  __restrict__ R,
                     float*        __restrict__ out,
                     int rows)
{
    __shared__ __align__(16) float tsh[NTT];
    __shared__ __align__(16) float csh[NTT];
    // per-row: [0]=a [1]=sprime [2]=q(=sp*dt) [3]=shift(=sp*TAU) [4..23]=C*d0..C*d19
    __shared__ float rc[ROWS_PER_BLK][RC_STRIDE];

    const int tid = threadIdx.x;

    // cooperative: time grid + combined weight c_j = R[j] * sin(deg2rad(alpha[j]))
    for (int j = tid; j < NTT; j += BLK) {
        tsh[j] = t[j];
        csh[j] = R[j] * __sinf(alpha[j] * F_DEG2RAD);
    }

    // per-row precompute (one lane per row) — cheap: 1 rcp + 1 div + 1 lg2 + 1 ex2
    if (tid < ROWS_PER_BLK) {
        int row = blockIdx.x * ROWS_PER_BLK + tid;
        if (row < rows) {
            float4 xv = x[row];
            float dt  = xv.x;
            float s   = xv.y;
            float p   = xv.z;
            float amp = xv.w;

            float u  = p * s;          // a - 1 in [0,1)
            float a  = 1.0f + u;
            float sp = s + F_INV_T1B;  // sprime

            // C = amp * 2 * exp(-dt/T1B) * (s/sp)^a   (base-2 form)
            float ratio = __fdividef(s, sp);
            float ex = fmaf(a, fast_lg2(ratio), -dt * (F_LOG2E * F_INV_T1B));
            float C  = amp * 2.0f * fast_ex2(ex);

            // Gamma(1+u), A&S 6.1.36 (|err| <= 3e-7 on [0,1])
            float g;
            g = fmaf(u,  0.035868343f, -0.193527818f);
            g = fmaf(u, g,  0.482199394f);
            g = fmaf(u, g, -0.756704078f);
            g = fmaf(u, g,  0.918206857f);
            g = fmaf(u, g, -0.897056937f);
            g = fmaf(u, g,  0.988205891f);
            g = fmaf(u, g, -0.577191652f);
            g = fmaf(u, g,  1.0f);

            // prod = Gamma(a+NTERMS) = Gamma(a+1) * prod_{k=1}^{NTERMS-1}(a+k)
            float prod = a * g;
            #pragma unroll
            for (int k = 1; k < NTERMS; k++) prod *= (a + (float)k);
            // single reciprocal, then build coefficients downward:
            // d_{NTERMS-1} = 1/Gamma(a+NTERMS);  d_{n-1} = d_n * (a+n)
            float d = __frcp_rn(prod);
            rc[tid][4 + NTERMS - 1] = C * d;
            #pragma unroll
            for (int n = NTERMS - 1; n >= 1; n--) {
                d *= (a + (float)n);
                rc[tid][4 + n - 1] = C * d;
            }

            rc[tid][0] = a;
            rc[tid][1] = sp;
            rc[tid][2] = sp * dt;
            rc[tid][3] = sp * F_TAU;
        }
    }
    __syncthreads();

    const int rl  = tid / THREADS_PER_ROW;
    const int l   = tid - rl * THREADS_PER_ROW;
    const int jj  = l * 4;
    const int row = blockIdx.x * ROWS_PER_BLK + rl;
    if (row >= rows) return;

    const float a     = rc[rl][0];
    const float sp    = rc[rl][1];
    const float q     = rc[rl][2];
    const float shift = rc[rl][3];

    // coefficients into REGISTERS once (C already folded in)
    unsigned long long D[NTERMS];
    #pragma unroll
    for (int k = 0; k < NTERMS; k++) {
        float dk = rc[rl][4 + k];
        D[k] = pack2(dk, dk);
    }

    const float4 t4 = *reinterpret_cast<const float4*>(tsh + jj);
    const float4 c4 = *reinterpret_cast<const float4*>(csh + jj);
    float tv[4] = {t4.x, t4.y, t4.z, t4.w};
    float cv[4] = {c4.x, c4.y, c4.z, c4.w};

    // 4 independent packed Horner chains for ILP
    float x1v[4], x2v[4];
    unsigned long long H[4];
    #pragma unroll
    for (int e = 0; e < 4; e++) {
        float x1 = fmaf(sp, tv[e], -q);          // sprime*(t_j - dt) > 0 always
        float x2 = fmaxf(x1 - shift, 0.0f);      // clamp as in reference
        x1v[e] = x1; x2v[e] = x2;
        H[e] = D[NTERMS - 1];
    }
    #pragma unroll
    for (int k = NTERMS - 2; k >= 0; k--) {
        #pragma unroll
        for (int e = 0; e < 4; e++)
            H[e] = ffma2(H[e], pack2(x1v[e], x2v[e]), D[k]);
    }

    float res[4];
    #pragma unroll
    for (int e = 0; e < 4; e++) {
        float h1, h2;
        unpack2(H[e], h1, h2);
        float x1 = x1v[e], x2 = x2v[e];
        // P(a,x)*C = exp2(a*log2(x) - x*log2e) * (C*H(x))
        // x2 == 0: lg2(0) = -inf -> ex2(-inf) = 0 -> P2 = 0  (no select needed)
        float v1 = fmaf(a, fast_lg2(x1), -x1 * F_LOG2E);
        float v2 = fmaf(a, fast_lg2(x2), -x2 * F_LOG2E);
        float P1 = fast_ex2(v1) * h1;
        float P2 = fast_ex2(v2) * h2;
        res[e] = cv[e] * (P1 - P2);
    }

    float4 o = make_float4(res[0], res[1], res[2], res[3]);
    *reinterpret_cast<float4*>(out + (size_t)row * NTT + jj) = o;
}

extern "C" void kernel_launch(void* const* d_in, const int* in_sizes, int n_in,
                              void* d_out, int out_size) {
    const float4* x     = (const float4*)d_in[0];
    const float*  t     = (const float*)d_in[1];
    const float*  alpha = (const float*)d_in[2];
    const float*  R     = (const float*)d_in[3];
    float* out = (float*)d_out;

    int rows   = in_sizes[0] / 4;
    int blocks = (rows + ROWS_PER_BLK - 1) / ROWS_PER_BLK;
    dynangio_kernel<<<blocks, BLK>>>(x, t, alpha, R, out, rows);
}

// round 3
// speedup vs baseline: 1.2139x; 1.2139x over previous
#include <cuda_runtime.h>
#include <cstdint>

#define NTT 144
#define NTERMS 20
#define RPB 16                    // rows per block
#define TPR 18                    // threads per row
#define EPT 8                     // elements per thread (2 groups of 4)
#define BLK (RPB * TPR)           // 288

#define F_TAU 1.8f
#define F_INV_T1B (1.0f/1.65f)
#define F_LOG2E 1.4426950408889634f
#define F_DEG2RAD 0.017453292519943295f

typedef unsigned long long ull;

__device__ __forceinline__ ull pack2(float lo, float hi) {
    ull r;
    asm("mov.b64 %0, {%1, %2};" : "=l"(r) : "f"(lo), "f"(hi));
    return r;
}
__device__ __forceinline__ void unpack2(ull v, float& lo, float& hi) {
    asm("mov.b64 {%0, %1}, %2;" : "=f"(lo), "=f"(hi) : "l"(v));
}
__device__ __forceinline__ ull ffma2(ull a, ull b, ull c) {
    ull d;
    asm("fma.rn.f32x2 %0, %1, %2, %3;" : "=l"(d) : "l"(a), "l"(b), "l"(c));
    return d;
}
__device__ __forceinline__ float fast_lg2(float x) {
    float r;
    asm("lg2.approx.f32 %0, %1;" : "=f"(r) : "f"(x));
    return r;
}
__device__ __forceinline__ float fast_ex2(float x) {
    float r;
    asm("ex2.approx.f32 %0, %1;" : "=f"(r) : "f"(x));
    return r;
}
// forced single load into a register pair — ptxas cannot rematerialize this
__device__ __forceinline__ ull lds64(uint32_t saddr) {
    ull v;
    asm volatile("ld.shared.b64 %0, [%1];" : "=l"(v) : "r"(saddr));
    return v;
}

__global__ __launch_bounds__(BLK, 2)
void dynangio_kernel(const float4* __restrict__ x,
                     const float*  __restrict__ t,
                     const float*  __restrict__ alpha,
                     const float*  __restrict__ R,
                     float*        __restrict__ out,
                     int rows)
{
    __shared__ __align__(16) float tsh[NTT];
    __shared__ __align__(16) float csh[NTT];
    // per-row packed coefficients {d,d} (C folded in), + packed scalars:
    // [20] = {a, sp}, [21] = {q, shift}
    __shared__ __align__(16) ull rcu[RPB][NTERMS + 2];

    const int tid = threadIdx.x;

    for (int j = tid; j < NTT; j += BLK) {
        tsh[j] = t[j];
        csh[j] = R[j] * __sinf(alpha[j] * F_DEG2RAD);
    }

    if (tid < RPB) {
        int row = blockIdx.x * RPB + tid;
        if (row < rows) {
            float4 xv = x[row];
            float dt  = xv.x;
            float s   = xv.y;
            float p   = xv.z;
            float amp = xv.w;

            float u  = p * s;          // a - 1 in [0,1)
            float a  = 1.0f + u;
            float sp = s + F_INV_T1B;  // sprime

            // C = amp * 2 * exp(-dt/T1B) * (s/sp)^a   (base-2)
            float ratio = __fdividef(s, sp);
            float ex = fmaf(a, fast_lg2(ratio), -dt * (F_LOG2E * F_INV_T1B));
            float C  = amp * 2.0f * fast_ex2(ex);

            // Gamma(1+u), A&S 6.1.36
            float g;
            g = fmaf(u,  0.035868343f, -0.193527818f);
            g = fmaf(u, g,  0.482199394f);
            g = fmaf(u, g, -0.756704078f);
            g = fmaf(u, g,  0.918206857f);
            g = fmaf(u, g, -0.897056937f);
            g = fmaf(u, g,  0.988205891f);
            g = fmaf(u, g, -0.577191652f);
            g = fmaf(u, g,  1.0f);

            // Gamma(a+NTERMS) by product, one reciprocal, build d_n downward
            float prod = a * g;
            #pragma unroll
            for (int k = 1; k < NTERMS; k++) prod *= (a + (float)k);
            float d = __frcp_rn(prod);
            float cd = C * d;
            rcu[tid][NTERMS - 1] = pack2(cd, cd);
            #pragma unroll
            for (int n = NTERMS - 1; n >= 1; n--) {
                d *= (a + (float)n);
                cd = C * d;
                rcu[tid][n - 1] = pack2(cd, cd);
            }
            rcu[tid][NTERMS]     = pack2(a, sp);
            rcu[tid][NTERMS + 1] = pack2(sp * dt, sp * F_TAU);
        }
    }
    __syncthreads();

    const int rl  = tid / TPR;
    const int l   = tid - rl * TPR;
    const int jj  = l * EPT;
    const int row = blockIdx.x * RPB + rl;
    if (row >= rows) return;

    const uint32_t rb = (uint32_t)__cvta_generic_to_shared(&rcu[rl][0]);

    // coefficients into pinned register pairs (cannot be rematerialized)
    ull D0  = lds64(rb +  0*8), D1  = lds64(rb +  1*8), D2  = lds64(rb +  2*8);
    ull D3  = lds64(rb +  3*8), D4  = lds64(rb +  4*8), D5  = lds64(rb +  5*8);
    ull D6  = lds64(rb +  6*8), D7  = lds64(rb +  7*8), D8  = lds64(rb +  8*8);
    ull D9  = lds64(rb +  9*8), D10 = lds64(rb + 10*8), D11 = lds64(rb + 11*8);
    ull D12 = lds64(rb + 12*8), D13 = lds64(rb + 13*8), D14 = lds64(rb + 14*8);
    ull D15 = lds64(rb + 15*8), D16 = lds64(rb + 16*8), D17 = lds64(rb + 17*8);
    ull D18 = lds64(rb + 18*8), D19 = lds64(rb + 19*8);
    ull SC0 = lds64(rb + 20*8), SC1 = lds64(rb + 21*8);

    float a, sp, q, shift;
    unpack2(SC0, a, sp);
    unpack2(SC1, q, shift);
    const float spl = sp * (-F_LOG2E);   // for m = -x1*log2e = fma(spl, t, ql)
    const float ql  = q * F_LOG2E;

    float* orow = out + (size_t)row * NTT + jj;

    #pragma unroll
    for (int g = 0; g < 2; g++) {
        const float4 t4 = *reinterpret_cast<const float4*>(tsh + jj + g * 4);
        const float4 c4 = *reinterpret_cast<const float4*>(csh + jj + g * 4);
        float tv[4] = {t4.x, t4.y, t4.z, t4.w};
        float cv[4] = {c4.x, c4.y, c4.z, c4.w};

        float x1v[4], x2v[4], m1v[4];
        ull X[4], H[4];
        #pragma unroll
        for (int e = 0; e < 4; e++) {
            float x1 = fmaf(sp, tv[e], -q);       // sprime*(t - dt) > 0
            float x2 = fmaxf(x1 - shift, 0.0f);
            x1v[e] = x1; x2v[e] = x2;
            m1v[e] = fmaf(spl, tv[e], ql);        // = -x1 * log2e (indep chain)
            X[e]   = pack2(x1, x2);
            H[e]   = D19;
        }

        #define HS(Dk) { H[0]=ffma2(H[0],X[0],Dk); H[1]=ffma2(H[1],X[1],Dk); \
                         H[2]=ffma2(H[2],X[2],Dk); H[3]=ffma2(H[3],X[3],Dk); }
        HS(D18) HS(D17) HS(D16) HS(D15) HS(D14) HS(D13) HS(D12) HS(D11)
        HS(D10) HS(D9)  HS(D8)  HS(D7)  HS(D6)  HS(D5)  HS(D4)  HS(D3)
        HS(D2)  HS(D1)  HS(D0)
        #undef HS

        float res[4];
        #pragma unroll
        for (int e = 0; e < 4; e++) {
            float h1, h2;
            unpack2(H[e], h1, h2);
            float x1 = x1v[e], x2 = x2v[e];
            // P*C = exp2(a*lg2(x) - x*log2e) * (C*H(x)); x2==0 -> ex2(-inf)=0
            float v1 = fmaf(a, fast_lg2(x1), m1v[e]);
            float v2 = fmaf(a, fast_lg2(x2), -x2 * F_LOG2E);
            float P1 = fast_ex2(v1) * h1;
            float P2 = fast_ex2(v2) * h2;
            res[e] = cv[e] * (P1 - P2);
        }
        float4 o = make_float4(res[0], res[1], res[2], res[3]);
        *reinterpret_cast<float4*>(orow + g * 4) = o;
    }
}

extern "C" void kernel_launch(void* const* d_in, const int* in_sizes, int n_in,
                              void* d_out, int out_size) {
    const float4* x     = (const float4*)d_in[0];
    const float*  t     = (const float*)d_in[1];
    const float*  alpha = (const float*)d_in[2];
    const float*  R     = (const float*)d_in[3];
    float* out = (float*)d_out;

    int rows   = in_sizes[0] / 4;
    int blocks = (rows + RPB - 1) / RPB;
    dynangio_kernel<<<blocks, BLK>>>(x, t, alpha, R, out, rows);
}

// round 4
// speedup vs baseline: 1.5320x; 1.2620x over previous
#include <cuda_runtime.h>
#include <cstdint>

#define NTT 144
#define NTERMS 18                 // truncation < 3e-5 abs at x_max=6.27
#define RPB 8                     // rows per block
#define TPR 18                    // threads per row
#define EPT 8                     // elements per thread (2 groups of 4)
#define BLK (RPB * TPR)           // 144

#define F_TAU 1.8f
#define F_INV_T1B (1.0f/1.65f)
#define F_LOG2E 1.4426950408889634f
#define F_DEG2RAD 0.017453292519943295f

typedef unsigned long long ull;

__device__ __forceinline__ ull pack2(float lo, float hi) {
    ull r;
    asm("mov.b64 %0, {%1, %2};" : "=l"(r) : "f"(lo), "f"(hi));
    return r;
}
__device__ __forceinline__ void unpack2(ull v, float& lo, float& hi) {
    asm("mov.b64 {%0, %1}, %2;" : "=f"(lo), "=f"(hi) : "l"(v));
}
__device__ __forceinline__ ull ffma2(ull a, ull b, ull c) {
    ull d;
    asm("fma.rn.f32x2 %0, %1, %2, %3;" : "=l"(d) : "l"(a), "l"(b), "l"(c));
    return d;
}
__device__ __forceinline__ float fast_lg2(float x) {
    float r;
    asm("lg2.approx.f32 %0, %1;" : "=f"(r) : "f"(x));
    return r;
}
__device__ __forceinline__ float fast_ex2(float x) {
    float r;
    asm("ex2.approx.f32 %0, %1;" : "=f"(r) : "f"(x));
    return r;
}
// forced single load into a register pair — ptxas cannot rematerialize this
__device__ __forceinline__ ull lds64(uint32_t saddr) {
    ull v;
    asm volatile("ld.shared.b64 %0, [%1];" : "=l"(v) : "r"(saddr));
    return v;
}

__global__ __launch_bounds__(BLK, 5)
void dynangio_kernel(const float4* __restrict__ x,
                     const float*  __restrict__ t,
                     const float*  __restrict__ alpha,
                     const float*  __restrict__ R,
                     float*        __restrict__ out,
                     int rows)
{
    __shared__ __align__(16) float tsh[NTT];
    __shared__ __align__(16) float csh[NTT];
    // per-row packed coefficients {d,d} (C folded in), + packed scalars:
    // [NTERMS] = {a, sp}, [NTERMS+1] = {q, shift}
    __shared__ __align__(16) ull rcu[RPB][NTERMS + 2];

    const int tid = threadIdx.x;

    for (int j = tid; j < NTT; j += BLK) {
        tsh[j] = t[j];
        csh[j] = R[j] * __sinf(alpha[j] * F_DEG2RAD);
    }

    if (tid < RPB) {
        int row = blockIdx.x * RPB + tid;
        if (row < rows) {
            float4 xv = x[row];
            float dt  = xv.x;
            float s   = xv.y;
            float p   = xv.z;
            float amp = xv.w;

            float u  = p * s;          // a - 1 in [0,1)
            float a  = 1.0f + u;
            float sp = s + F_INV_T1B;  // sprime

            // C = amp * 2 * exp(-dt/T1B) * (s/sp)^a   (base-2)
            float ratio = __fdividef(s, sp);
            float ex = fmaf(a, fast_lg2(ratio), -dt * (F_LOG2E * F_INV_T1B));
            float C  = amp * 2.0f * fast_ex2(ex);

            // Gamma(1+u), A&S 6.1.36
            float g;
            g = fmaf(u,  0.035868343f, -0.193527818f);
            g = fmaf(u, g,  0.482199394f);
            g = fmaf(u, g, -0.756704078f);
            g = fmaf(u, g,  0.918206857f);
            g = fmaf(u, g, -0.897056937f);
            g = fmaf(u, g,  0.988205891f);
            g = fmaf(u, g, -0.577191652f);
            g = fmaf(u, g,  1.0f);

            // Gamma(a+NTERMS) by product, one reciprocal, build d_n downward
            float prod = a * g;
            #pragma unroll
            for (int k = 1; k < NTERMS; k++) prod *= (a + (float)k);
            float d = __frcp_rn(prod);
            float cd = C * d;
            rcu[tid][NTERMS - 1] = pack2(cd, cd);
            #pragma unroll
            for (int n = NTERMS - 1; n >= 1; n--) {
                d *= (a + (float)n);
                cd = C * d;
                rcu[tid][n - 1] = pack2(cd, cd);
            }
            rcu[tid][NTERMS]     = pack2(a, sp);
            rcu[tid][NTERMS + 1] = pack2(sp * dt, sp * F_TAU);
        }
    }
    __syncthreads();

    const int rl  = tid / TPR;
    const int l   = tid - rl * TPR;
    const int jj  = l * EPT;
    const int row = blockIdx.x * RPB + rl;
    if (row >= rows) return;

    const uint32_t rb = (uint32_t)__cvta_generic_to_shared(&rcu[rl][0]);

    // coefficients into pinned register pairs (cannot be rematerialized)
    ull D0  = lds64(rb +  0*8), D1  = lds64(rb +  1*8), D2  = lds64(rb +  2*8);
    ull D3  = lds64(rb +  3*8), D4  = lds64(rb +  4*8), D5  = lds64(rb +  5*8);
    ull D6  = lds64(rb +  6*8), D7  = lds64(rb +  7*8), D8  = lds64(rb +  8*8);
    ull D9  = lds64(rb +  9*8), D10 = lds64(rb + 10*8), D11 = lds64(rb + 11*8);
    ull D12 = lds64(rb + 12*8), D13 = lds64(rb + 13*8), D14 = lds64(rb + 14*8);
    ull D15 = lds64(rb + 15*8), D16 = lds64(rb + 16*8), D17 = lds64(rb + 17*8);
    ull SC0 = lds64(rb + NTERMS*8), SC1 = lds64(rb + (NTERMS+1)*8);

    float a, sp, q, shift;
    unpack2(SC0, a, sp);
    unpack2(SC1, q, shift);
    const float spl = sp * (-F_LOG2E);   // m1 = -x1*log2e = fma(spl, t, ql)
    const float ql  = q * F_LOG2E;
    const float sl  = shift * F_LOG2E;   // m2 = m1 + sl  (since x2 = x1 - shift)

    float* orow = out + (size_t)row * NTT + jj;

    #pragma unroll
    for (int g = 0; g < 2; g++) {
        const float4 t4 = *reinterpret_cast<const float4*>(tsh + jj + g * 4);
        const float4 c4 = *reinterpret_cast<const float4*>(csh + jj + g * 4);
        float tv[4] = {t4.x, t4.y, t4.z, t4.w};
        float cv[4] = {c4.x, c4.y, c4.z, c4.w};

        float x1v[4], x2v[4], m1v[4];
        ull X[4], H[4];
        #pragma unroll
        for (int e = 0; e < 4; e++) {
            float x1 = fmaf(sp, tv[e], -q);       // sprime*(t - dt) > 0
            float x2 = fmaxf(x1 - shift, 0.0f);
            x1v[e] = x1; x2v[e] = x2;
            m1v[e] = fmaf(spl, tv[e], ql);        // = -x1 * log2e (indep chain)
            X[e]   = pack2(x1, x2);
            H[e]   = D17;
        }

        #define HS(Dk) { H[0]=ffma2(H[0],X[0],Dk); H[1]=ffma2(H[1],X[1],Dk); \
                         H[2]=ffma2(H[2],X[2],Dk); H[3]=ffma2(H[3],X[3],Dk); }
        HS(D16) HS(D15) HS(D14) HS(D13) HS(D12) HS(D11)
        HS(D10) HS(D9)  HS(D8)  HS(D7)  HS(D6)  HS(D5)
        HS(D4)  HS(D3)  HS(D2)  HS(D1)  HS(D0)
        #undef HS

        float res[4];
        #pragma unroll
        for (int e = 0; e < 4; e++) {
            float h1, h2;
            unpack2(H[e], h1, h2);
            float x1 = x1v[e], x2 = x2v[e];
            // P*C = exp2(a*lg2(x) - x*log2e) * (C*H(x)); x2==0 -> ex2(-inf)=0
            float v1 = fmaf(a, fast_lg2(x1), m1v[e]);
            float v2 = fmaf(a, fast_lg2(x2), m1v[e] + sl);
            float P1 = fast_ex2(v1) * h1;
            float P2 = fast_ex2(v2) * h2;
            res[e] = cv[e] * (P1 - P2);
        }
        float4 o = make_float4(res[0], res[1], res[2], res[3]);
        *reinterpret_cast<float4*>(orow + g * 4) = o;
    }
}

extern "C" void kernel_launch(void* const* d_in, const int* in_sizes, int n_in,
                              void* d_out, int out_size) {
    const float4* x     = (const float4*)d_in[0];
    const float*  t     = (const float*)d_in[1];
    const float*  alpha = (const float*)d_in[2];
    const float*  R     = (const float*)d_in[3];
    float* out = (float*)d_out;

    int rows   = in_sizes[0] / 4;
    int blocks = (rows + RPB - 1) / RPB;
    dynangio_kernel<<<blocks, BLK>>>(x, t, alpha, R, out, rows);
}

// round 5
// speedup vs baseline: 1.7567x; 1.1467x over previous
#include <cuda_runtime.h>
#include <cstdint>

#define NTT 144
#define NTERMS 16                 // tail ~3e-4 abs worst-elem; global rel ~2e-5
#define RPB 8                     // rows per block
#define TPR 18                    // threads per row
#define EPT 8                     // elements per thread (2 groups of 4)
#define BLK (RPB * TPR)           // 144

#define F_TAU 1.8f
#define F_INV_T1B (1.0f/1.65f)
#define F_LOG2E 1.4426950408889634f
#define F_DEG2RAD 0.017453292519943295f

typedef unsigned long long ull;

__device__ __forceinline__ ull pack2(float lo, float hi) {
    ull r;
    asm("mov.b64 %0, {%1, %2};" : "=l"(r) : "f"(lo), "f"(hi));
    return r;
}
__device__ __forceinline__ void unpack2(ull v, float& lo, float& hi) {
    asm("mov.b64 {%0, %1}, %2;" : "=f"(lo), "=f"(hi) : "l"(v));
}
__device__ __forceinline__ ull ffma2(ull a, ull b, ull c) {
    ull d;
    asm("fma.rn.f32x2 %0, %1, %2, %3;" : "=l"(d) : "l"(a), "l"(b), "l"(c));
    return d;
}
__device__ __forceinline__ float fast_lg2(float x) {
    float r;
    asm("lg2.approx.f32 %0, %1;" : "=f"(r) : "f"(x));
    return r;
}
__device__ __forceinline__ float fast_ex2(float x) {
    float r;
    asm("ex2.approx.f32 %0, %1;" : "=f"(r) : "f"(x));
    return r;
}
// forced single load into a register pair — ptxas cannot rematerialize this
__device__ __forceinline__ ull lds64(uint32_t saddr) {
    ull v;
    asm volatile("ld.shared.b64 %0, [%1];" : "=l"(v) : "r"(saddr));
    return v;
}

__global__ __launch_bounds__(BLK, 7)
void dynangio_kernel(const float4* __restrict__ x,
                     const float*  __restrict__ t,
                     const float*  __restrict__ alpha,
                     const float*  __restrict__ R,
                     float*        __restrict__ out,
                     int rows)
{
    __shared__ __align__(16) float tsh[NTT];
    __shared__ __align__(16) float csh[NTT];
    // per-row packed coefficients {d,d} (C folded in), + packed scalars:
    // [NTERMS] = {a, sp}, [NTERMS+1] = {q, shift}
    __shared__ __align__(16) ull rcu[RPB][NTERMS + 2];

    const int tid = threadIdx.x;

    for (int j = tid; j < NTT; j += BLK) {
        tsh[j] = t[j];
        csh[j] = R[j] * __sinf(alpha[j] * F_DEG2RAD);
    }

    if (tid < RPB) {
        int row = blockIdx.x * RPB + tid;
        if (row < rows) {
            float4 xv = x[row];
            float dt  = xv.x;
            float s   = xv.y;
            float p   = xv.z;
            float amp = xv.w;

            float u  = p * s;          // a - 1 in [0,1)
            float a  = 1.0f + u;
            float sp = s + F_INV_T1B;  // sprime

            // C = amp * 2 * exp(-dt/T1B) * (s/sp)^a   (base-2)
            float ratio = __fdividef(s, sp);
            float ex = fmaf(a, fast_lg2(ratio), -dt * (F_LOG2E * F_INV_T1B));
            float C  = amp * 2.0f * fast_ex2(ex);

            // Gamma(1+u), A&S 6.1.36
            float g;
            g = fmaf(u,  0.035868343f, -0.193527818f);
            g = fmaf(u, g,  0.482199394f);
            g = fmaf(u, g, -0.756704078f);
            g = fmaf(u, g,  0.918206857f);
            g = fmaf(u, g, -0.897056937f);
            g = fmaf(u, g,  0.988205891f);
            g = fmaf(u, g, -0.577191652f);
            g = fmaf(u, g,  1.0f);

            // Gamma(a+NTERMS) by product, one reciprocal, build d_n downward
            float prod = a * g;
            #pragma unroll
            for (int k = 1; k < NTERMS; k++) prod *= (a + (float)k);
            float d = __frcp_rn(prod);
            float cd = C * d;
            rcu[tid][NTERMS - 1] = pack2(cd, cd);
            #pragma unroll
            for (int n = NTERMS - 1; n >= 1; n--) {
                d *= (a + (float)n);
                cd = C * d;
                rcu[tid][n - 1] = pack2(cd, cd);
            }
            rcu[tid][NTERMS]     = pack2(a, sp);
            rcu[tid][NTERMS + 1] = pack2(sp * dt, sp * F_TAU);
        }
    }
    __syncthreads();

    const int rl  = tid / TPR;
    const int l   = tid - rl * TPR;
    const int jj  = l * EPT;
    const int row = blockIdx.x * RPB + rl;
    if (row >= rows) return;

    const uint32_t rb = (uint32_t)__cvta_generic_to_shared(&rcu[rl][0]);

    // coefficients into pinned register pairs (cannot be rematerialized)
    ull D0  = lds64(rb +  0*8), D1  = lds64(rb +  1*8), D2  = lds64(rb +  2*8);
    ull D3  = lds64(rb +  3*8), D4  = lds64(rb +  4*8), D5  = lds64(rb +  5*8);
    ull D6  = lds64(rb +  6*8), D7  = lds64(rb +  7*8), D8  = lds64(rb +  8*8);
    ull D9  = lds64(rb +  9*8), D10 = lds64(rb + 10*8), D11 = lds64(rb + 11*8);
    ull D12 = lds64(rb + 12*8), D13 = lds64(rb + 13*8), D14 = lds64(rb + 14*8);
    ull D15 = lds64(rb + 15*8);
    ull SC0 = lds64(rb + NTERMS*8), SC1 = lds64(rb + (NTERMS+1)*8);

    float a, sp, q, shift;
    unpack2(SC0, a, sp);
    unpack2(SC1, q, shift);

    float* orow = out + (size_t)row * NTT + jj;

    #pragma unroll
    for (int g = 0; g < 2; g++) {
        const float4 t4 = *reinterpret_cast<const float4*>(tsh + jj + g * 4);

        ull X[4], H[4];
        {
            float tv0 = t4.x, tv1 = t4.y, tv2 = t4.z, tv3 = t4.w;
            float a0 = fmaf(sp, tv0, -q), a1 = fmaf(sp, tv1, -q);
            float a2 = fmaf(sp, tv2, -q), a3 = fmaf(sp, tv3, -q);
            X[0] = pack2(a0, fmaxf(a0 - shift, 0.0f));
            X[1] = pack2(a1, fmaxf(a1 - shift, 0.0f));
            X[2] = pack2(a2, fmaxf(a2 - shift, 0.0f));
            X[3] = pack2(a3, fmaxf(a3 - shift, 0.0f));
            H[0] = D15; H[1] = D15; H[2] = D15; H[3] = D15;
        }

        #define HS(Dk) { H[0]=ffma2(H[0],X[0],Dk); H[1]=ffma2(H[1],X[1],Dk); \
                         H[2]=ffma2(H[2],X[2],Dk); H[3]=ffma2(H[3],X[3],Dk); }
        HS(D14) HS(D13) HS(D12) HS(D11)
        HS(D10) HS(D9)  HS(D8)  HS(D7)  HS(D6)  HS(D5)
        HS(D4)  HS(D3)  HS(D2)  HS(D1)  HS(D0)
        #undef HS

        const float4 c4 = *reinterpret_cast<const float4*>(csh + jj + g * 4);
        float cv[4] = {c4.x, c4.y, c4.z, c4.w};

        float res[4];
        #pragma unroll
        for (int e = 0; e < 4; e++) {
            float h1, h2, x1, x2;
            unpack2(H[e], h1, h2);
            unpack2(X[e], x1, x2);
            // P*C = exp2(a*lg2(x) - x*log2e) * (C*H(x)); x2==0 -> ex2(-inf)=0
            float v1 = fmaf(a, fast_lg2(x1), -x1 * F_LOG2E);
            float v2 = fmaf(a, fast_lg2(x2), -x2 * F_LOG2E);
            float P1 = fast_ex2(v1) * h1;
            float P2 = fast_ex2(v2) * h2;
            res[e] = cv[e] * (P1 - P2);
        }
        float4 o = make_float4(res[0], res[1], res[2], res[3]);
        *reinterpret_cast<float4*>(orow + g * 4) = o;
    }
}

extern "C" void kernel_launch(void* const* d_in, const int* in_sizes, int n_in,
                              void* d_out, int out_size) {
    const float4* x     = (const float4*)d_in[0];
    const float*  t     = (const float*)d_in[1];
    const float*  alpha = (const float*)d_in[2];
    const float*  R     = (const float*)d_in[3];
    float* out = (float*)d_out;

    int rows   = in_sizes[0] / 4;
    int blocks = (rows + RPB - 1) / RPB;
    dynangio_kernel<<<blocks, BLK>>>(x, t, alpha, R, out, rows);
}

// round 6
// speedup vs baseline: 1.8658x; 1.0621x over previous
#include <cuda_runtime.h>
#include <cstdint>

#define NTT 144
#define NTERMS 14                 // tail ~1.6e-4 rel predicted (6x margin)
#define RPB 16                    // rows per block
#define TPR 9                     // threads per row
#define EPT 16                    // elements per thread (4 groups of 4)
#define BLK (RPB * TPR)           // 144

#define F_TAU 1.8f
#define F_INV_T1B (1.0f/1.65f)
#define F_LOG2E 1.4426950408889634f
#define F_DEG2RAD 0.017453292519943295f

typedef unsigned long long ull;

__device__ __forceinline__ ull pack2(float lo, float hi) {
    ull r;
    asm("mov.b64 %0, {%1, %2};" : "=l"(r) : "f"(lo), "f"(hi));
    return r;
}
__device__ __forceinline__ void unpack2(ull v, float& lo, float& hi) {
    asm("mov.b64 {%0, %1}, %2;" : "=f"(lo), "=f"(hi) : "l"(v));
}
__device__ __forceinline__ ull ffma2(ull a, ull b, ull c) {
    ull d;
    asm("fma.rn.f32x2 %0, %1, %2, %3;" : "=l"(d) : "l"(a), "l"(b), "l"(c));
    return d;
}
__device__ __forceinline__ float fast_lg2(float x) {
    float r;
    asm("lg2.approx.f32 %0, %1;" : "=f"(r) : "f"(x));
    return r;
}
__device__ __forceinline__ float fast_ex2(float x) {
    float r;
    asm("ex2.approx.f32 %0, %1;" : "=f"(r) : "f"(x));
    return r;
}
// forced single load into a register pair — ptxas cannot rematerialize this
__device__ __forceinline__ ull lds64(uint32_t saddr) {
    ull v;
    asm volatile("ld.shared.b64 %0, [%1];" : "=l"(v) : "r"(saddr));
    return v;
}

__global__ __launch_bounds__(BLK, 8)
void dynangio_kernel(const float4* __restrict__ x,
                     const float*  __restrict__ t,
                     const float*  __restrict__ alpha,
                     const float*  __restrict__ R,
                     float*        __restrict__ out,
                     int rows)
{
    __shared__ __align__(16) float tsh[NTT];
    __shared__ __align__(16) float csh[NTT];
    // per-row packed coefficients {d,d} (C folded in), + packed scalars:
    // [NTERMS] = {a, sp}, [NTERMS+1] = {q, shift}
    __shared__ __align__(16) ull rcu[RPB][NTERMS + 2];

    const int tid = threadIdx.x;

    for (int j = tid; j < NTT; j += BLK) {
        tsh[j] = t[j];
        csh[j] = R[j] * __sinf(alpha[j] * F_DEG2RAD);
    }

    if (tid < RPB) {
        int row = blockIdx.x * RPB + tid;
        if (row < rows) {
            float4 xv = x[row];
            float dt  = xv.x;
            float s   = xv.y;
            float p   = xv.z;
            float amp = xv.w;

            float u  = p * s;          // a - 1 in [0,1)
            float a  = 1.0f + u;
            float sp = s + F_INV_T1B;  // sprime

            // C = amp * 2 * exp(-dt/T1B) * (s/sp)^a   (base-2)
            float ratio = __fdividef(s, sp);
            float ex = fmaf(a, fast_lg2(ratio), -dt * (F_LOG2E * F_INV_T1B));
            float C  = amp * 2.0f * fast_ex2(ex);

            // Gamma(1+u), A&S 6.1.36
            float g;
            g = fmaf(u,  0.035868343f, -0.193527818f);
            g = fmaf(u, g,  0.482199394f);
            g = fmaf(u, g, -0.756704078f);
            g = fmaf(u, g,  0.918206857f);
            g = fmaf(u, g, -0.897056937f);
            g = fmaf(u, g,  0.988205891f);
            g = fmaf(u, g, -0.577191652f);
            g = fmaf(u, g,  1.0f);

            // Gamma(a+NTERMS) by product, one reciprocal, build d_n downward
            float prod = a * g;
            #pragma unroll
            for (int k = 1; k < NTERMS; k++) prod *= (a + (float)k);
            float d = __frcp_rn(prod);
            float cd = C * d;
            rcu[tid][NTERMS - 1] = pack2(cd, cd);
            #pragma unroll
            for (int n = NTERMS - 1; n >= 1; n--) {
                d *= (a + (float)n);
                cd = C * d;
                rcu[tid][n - 1] = pack2(cd, cd);
            }
            rcu[tid][NTERMS]     = pack2(a, sp);
            rcu[tid][NTERMS + 1] = pack2(sp * dt, sp * F_TAU);
        }
    }
    __syncthreads();

    const int rl  = tid / TPR;
    const int l   = tid - rl * TPR;
    const int jj  = l * EPT;
    const int row = blockIdx.x * RPB + rl;
    if (row >= rows) return;

    const uint32_t rb = (uint32_t)__cvta_generic_to_shared(&rcu[rl][0]);

    // coefficients into pinned register pairs (cannot be rematerialized)
    ull D0  = lds64(rb +  0*8), D1  = lds64(rb +  1*8), D2  = lds64(rb +  2*8);
    ull D3  = lds64(rb +  3*8), D4  = lds64(rb +  4*8), D5  = lds64(rb +  5*8);
    ull D6  = lds64(rb +  6*8), D7  = lds64(rb +  7*8), D8  = lds64(rb +  8*8);
    ull D9  = lds64(rb +  9*8), D10 = lds64(rb + 10*8), D11 = lds64(rb + 11*8);
    ull D12 = lds64(rb + 12*8), D13 = lds64(rb + 13*8);
    ull SC0 = lds64(rb + NTERMS*8), SC1 = lds64(rb + (NTERMS+1)*8);

    float a, sp, q, shift;
    unpack2(SC0, a, sp);
    unpack2(SC1, q, shift);

    float* orow = out + (size_t)row * NTT + jj;

    #pragma unroll
    for (int g = 0; g < 4; g++) {
        const float4 t4 = *reinterpret_cast<const float4*>(tsh + jj + g * 4);

        ull X[4], H[4];
        {
            float a0 = fmaf(sp, t4.x, -q), a1 = fmaf(sp, t4.y, -q);
            float a2 = fmaf(sp, t4.z, -q), a3 = fmaf(sp, t4.w, -q);
            X[0] = pack2(a0, fmaxf(a0 - shift, 0.0f));
            X[1] = pack2(a1, fmaxf(a1 - shift, 0.0f));
            X[2] = pack2(a2, fmaxf(a2 - shift, 0.0f));
            X[3] = pack2(a3, fmaxf(a3 - shift, 0.0f));
            H[0] = D13; H[1] = D13; H[2] = D13; H[3] = D13;
        }

        #define HS(Dk) { H[0]=ffma2(H[0],X[0],Dk); H[1]=ffma2(H[1],X[1],Dk); \
                         H[2]=ffma2(H[2],X[2],Dk); H[3]=ffma2(H[3],X[3],Dk); }
        HS(D12) HS(D11) HS(D10) HS(D9)  HS(D8)  HS(D7)
        HS(D6)  HS(D5)  HS(D4)  HS(D3)  HS(D2)  HS(D1)  HS(D0)
        #undef HS

        const float4 c4 = *reinterpret_cast<const float4*>(csh + jj + g * 4);
        float cv[4] = {c4.x, c4.y, c4.z, c4.w};

        float res[4];
        #pragma unroll
        for (int e = 0; e < 4; e++) {
            float h1, h2, x1, x2;
            unpack2(H[e], h1, h2);
            unpack2(X[e], x1, x2);
            // P*C = exp2(a*lg2(x) - x*log2e) * (C*H(x)); x2==0 -> ex2(-inf)=0
            float v1 = fmaf(a, fast_lg2(x1), -x1 * F_LOG2E);
            float v2 = fmaf(a, fast_lg2(x2), -x2 * F_LOG2E);
            float P1 = fast_ex2(v1) * h1;
            float P2 = fast_ex2(v2) * h2;
            res[e] = cv[e] * (P1 - P2);
        }
        float4 o = make_float4(res[0], res[1], res[2], res[3]);
        *reinterpret_cast<float4*>(orow + g * 4) = o;
    }
}

extern "C" void kernel_launch(void* const* d_in, const int* in_sizes, int n_in,
                              void* d_out, int out_size) {
    const float4* x     = (const float4*)d_in[0];
    const float*  t     = (const float*)d_in[1];
    const float*  alpha = (const float*)d_in[2];
    const float*  R     = (const float*)d_in[3];
    float* out = (float*)d_out;

    int rows   = in_sizes[0] / 4;
    int blocks = (rows + RPB - 1) / RPB;
    dynangio_kernel<<<blocks, BLK>>>(x, t, alpha, R, out, rows);
}